// round 1
// baseline (speedup 1.0000x reference)
#include <cuda_runtime.h>
#include <cstdint>

#define N_NODES 4096
#define D_IN    256
#define D_OUT   128
#define H_HEADS 4
#define NEG_SLOPE 0.2f
#define NWORDS  (N_NODES / 32)

typedef unsigned long long u64;

// ---------------- scratch (device globals; no allocation allowed) ----------------
__device__ float    g_h[H_HEADS * N_NODES * D_OUT];   // 8 MB   h[head][j][o]
__device__ unsigned g_mask[N_NODES * NWORDS];          // 2 MB   bit j of row i
__device__ float    g_si [H_HEADS * N_NODES];
__device__ float    g_Ei [H_HEADS * N_NODES];          // exp(s_i)
__device__ float    g_Ei2[H_HEADS * N_NODES];          // exp(0.2*s_i)
__device__ float4   g_jp [H_HEADS * N_NODES];          // (s_j, exp(s_j), exp(0.2*s_j), 0)

// ---------------- f32x2 helpers (Blackwell packed fp32) ----------------
__device__ __forceinline__ u64 packf2(float lo, float hi) {
    u64 r; asm("mov.b64 %0, {%1, %2};" : "=l"(r) : "f"(lo), "f"(hi)); return r;
}
__device__ __forceinline__ void unpackf2(u64 v, float& lo, float& hi) {
    asm("mov.b64 {%0, %1}, %2;" : "=f"(lo), "=f"(hi) : "l"(v));
}
__device__ __forceinline__ u64 fma2(u64 a, u64 b, u64 c) {
    u64 r; asm("fma.rn.f32x2 %0, %1, %2, %3;" : "=l"(r) : "l"(a), "l"(b), "l"(c)); return r;
}

// ---------------- kernel 1: bit-pack mask = (A>0) | eye ----------------
__global__ void pack_mask_kernel(const int* __restrict__ A) {
    int g    = blockIdx.x * blockDim.x + threadIdx.x;   // 16.7M threads
    int lane = g & 31;
    int word = g >> 5;               // 0 .. 4096*128-1
    int row  = word >> 7;
    int jw   = word & 127;
    int j    = jw * 32 + lane;
    int v = (A[row * N_NODES + j] > 0) || (j == row);
    unsigned b = __ballot_sync(0xffffffffu, v);
    if (lane == 0) g_mask[word] = b;
}

// ---------------- kernel 2: h = x @ W per head (fp32 tiled GEMM) ----------------
__global__ __launch_bounds__(256) void h_gemm_kernel(const float* __restrict__ x,
                                                     const float* __restrict__ W) {
    __shared__ __align__(16) float xs[32][129];   // [k][row], pad kills STS conflicts
    __shared__ __align__(16) float ws[32][128];   // [k][o]
    int head    = blockIdx.y;
    int rowbase = blockIdx.x * 128;
    int tid = threadIdx.x;
    int tx  = tid & 15;            // o group: o0 = tx*8
    int ty  = tid >> 4;            // 0..15 ; rows = ty + u*16
    int o0  = tx * 8;

    float acc[8][8];
#pragma unroll
    for (int u = 0; u < 8; u++)
#pragma unroll
        for (int i = 0; i < 8; i++) acc[u][i] = 0.f;

    const float* Wh = W + head * D_IN * D_OUT;

    for (int k0 = 0; k0 < D_IN; k0 += 32) {
        __syncthreads();
        // x tile: 128 rows x 32 k  (coalesced float4 reads, transposed store)
#pragma unroll
        for (int u = 0; u < 4; u++) {
            int e4  = tid + u * 256;          // 0..1023
            int row = e4 >> 3, kq = e4 & 7;
            float4 v = *(const float4*)&x[(rowbase + row) * D_IN + k0 + kq * 4];
            xs[kq * 4 + 0][row] = v.x;
            xs[kq * 4 + 1][row] = v.y;
            xs[kq * 4 + 2][row] = v.z;
            xs[kq * 4 + 3][row] = v.w;
        }
        // W tile: 32 k x 128 o (coalesced)
#pragma unroll
        for (int u = 0; u < 4; u++) {
            int e4 = tid + u * 256;
            int kk = e4 >> 5, oq = e4 & 31;
            *(float4*)&ws[kk][oq * 4] = *(const float4*)&Wh[(k0 + kk) * D_OUT + oq * 4];
        }
        __syncthreads();
#pragma unroll
        for (int kk = 0; kk < 32; kk++) {
            float wv[8];
            *(float4*)&wv[0] = *(const float4*)&ws[kk][o0];
            *(float4*)&wv[4] = *(const float4*)&ws[kk][o0 + 4];
#pragma unroll
            for (int u = 0; u < 8; u++) {
                float xv = xs[kk][ty + u * 16];
#pragma unroll
                for (int i = 0; i < 8; i++) acc[u][i] += xv * wv[i];
            }
        }
    }
#pragma unroll
    for (int u = 0; u < 8; u++) {
        int row = rowbase + ty + u * 16;
        float* dst = &g_h[(head * N_NODES + row) * D_OUT + o0];
        *(float4*)&dst[0] = make_float4(acc[u][0], acc[u][1], acc[u][2], acc[u][3]);
        *(float4*)&dst[4] = make_float4(acc[u][4], acc[u][5], acc[u][6], acc[u][7]);
    }
}

// ---------------- kernel 3: s_i, s_j and separable exp factors ----------------
__global__ void sij_kernel(const float* __restrict__ a) {
    int head = blockIdx.y;
    int warp = threadIdx.x >> 5, lane = threadIdx.x & 31;
    int row  = blockIdx.x * 8 + warp;
    const float* hrow = &g_h[(head * N_NODES + row) * D_OUT];
    const float* ah   = a + head * 2 * D_OUT;   // a[h][0:128]=a1, a[h][128:256]=a2
    float s1 = 0.f, s2 = 0.f;
#pragma unroll
    for (int u = 0; u < 4; u++) {
        int o = lane + u * 32;
        float hv = hrow[o];
        s1 += hv * ah[o];
        s2 += hv * ah[D_OUT + o];
    }
#pragma unroll
    for (int off = 16; off; off >>= 1) {
        s1 += __shfl_xor_sync(0xffffffffu, s1, off);
        s2 += __shfl_xor_sync(0xffffffffu, s2, off);
    }
    if (lane == 0) {
        g_si [head * N_NODES + row] = s1;
        g_Ei [head * N_NODES + row] = expf(s1);
        g_Ei2[head * N_NODES + row] = expf(NEG_SLOPE * s1);
        g_jp [head * N_NODES + row] = make_float4(s2, expf(s2), expf(NEG_SLOPE * s2), 0.f);
    }
}

// ---------------- kernel 4: fused masked-softmax aggregation ----------------
// Grid (64, 4): block = 64 rows x one head. 128 threads: tx in [0,4) -> 32 outputs,
// ty in [0,32) -> 2 rows. Weights generated on the fly; f32x2 packed FMA.
__global__ __launch_bounds__(128) void agg_kernel(float* __restrict__ out) {
    __shared__ __align__(16) float  hsm[32 * 128];   // 32 j x 128 o tile
    __shared__ __align__(16) float4 psm[32];         // (sj, Ej, Ej2) per j

    int head    = blockIdx.y;
    int rowbase = blockIdx.x * 64;
    int tid = threadIdx.x;
    int tx  = tid & 3;
    int ty  = tid >> 2;
    int o0  = tx * 32;
    int r0  = rowbase + ty * 2, r1 = r0 + 1;

    float si0  = g_si [head * N_NODES + r0], si1  = g_si [head * N_NODES + r1];
    float Ei0  = g_Ei [head * N_NODES + r0], Ei1  = g_Ei [head * N_NODES + r1];
    float Ei20 = g_Ei2[head * N_NODES + r0], Ei21 = g_Ei2[head * N_NODES + r1];

    u64 acc0[16], acc1[16];
#pragma unroll
    for (int k = 0; k < 16; k++) { acc0[k] = 0ull; acc1[k] = 0ull; }
    float Z0 = 0.f, Z1 = 0.f;

    const float4* hsrc = (const float4*)&g_h[head * N_NODES * D_OUT];
    const float4* jpb  = &g_jp[head * N_NODES];

    for (int jt = 0; jt < N_NODES; jt += 32) {
        __syncthreads();
        {   // stage h tile (4096 floats = 1024 float4) + j params
            const float4* src = hsrc + jt * (D_OUT / 4);
            float4* dst = (float4*)hsm;
#pragma unroll
            for (int u = 0; u < 8; u++) dst[tid + u * 128] = src[tid + u * 128];
            if (tid < 32) psm[tid] = jpb[jt + tid];
        }
        __syncthreads();

        unsigned m0 = g_mask[r0 * NWORDS + (jt >> 5)];
        unsigned m1 = g_mask[r1 * NWORDS + (jt >> 5)];

#pragma unroll 8
        for (int jj = 0; jj < 32; jj++) {
            float4 p = psm[jj];
            float t0 = si0 + p.x;
            float v0 = (t0 > 0.f) ? (Ei0 * p.y) : (Ei20 * p.z);
            float w0 = ((m0 >> jj) & 1u) ? v0 : 0.f;
            float t1 = si1 + p.x;
            float v1 = (t1 > 0.f) ? (Ei1 * p.y) : (Ei21 * p.z);
            float w1 = ((m1 >> jj) & 1u) ? v1 : 0.f;
            Z0 += w0; Z1 += w1;
            u64 pw0 = packf2(w0, w0);
            u64 pw1 = packf2(w1, w1);
            const ulonglong2* hp = (const ulonglong2*)(hsm + jj * 128 + o0);
#pragma unroll
            for (int k = 0; k < 8; k++) {
                ulonglong2 hv = hp[k];
                acc0[2 * k    ] = fma2(pw0, hv.x, acc0[2 * k    ]);
                acc0[2 * k + 1] = fma2(pw0, hv.y, acc0[2 * k + 1]);
                acc1[2 * k    ] = fma2(pw1, hv.x, acc1[2 * k    ]);
                acc1[2 * k + 1] = fma2(pw1, hv.y, acc1[2 * k + 1]);
            }
        }
    }

    float inv0 = 1.f / Z0, inv1 = 1.f / Z1;
    float* out0 = out + r0 * (H_HEADS * D_OUT) + head * D_OUT + o0;
    float* out1 = out + r1 * (H_HEADS * D_OUT) + head * D_OUT + o0;
#pragma unroll
    for (int k = 0; k < 8; k++) {
        float a0, b0, c0, d0, a1f, b1f, c1f, d1f;
        unpackf2(acc0[2 * k],     a0, b0);
        unpackf2(acc0[2 * k + 1], c0, d0);
        unpackf2(acc1[2 * k],     a1f, b1f);
        unpackf2(acc1[2 * k + 1], c1f, d1f);
        *(float4*)&out0[4 * k] = make_float4(a0 * inv0, b0 * inv0, c0 * inv0, d0 * inv0);
        *(float4*)&out1[4 * k] = make_float4(a1f * inv1, b1f * inv1, c1f * inv1, d1f * inv1);
    }
}

// ---------------- launch ----------------
extern "C" void kernel_launch(void* const* d_in, const int* in_sizes, int n_in,
                              void* d_out, int out_size) {
    const float* x = (const float*)d_in[0];
    const int*   A = (const int*)  d_in[1];
    const float* W = (const float*)d_in[2];
    const float* a = (const float*)d_in[3];
    float* out = (float*)d_out;

    pack_mask_kernel<<<(N_NODES * N_NODES) / 256, 256>>>(A);
    h_gemm_kernel<<<dim3(N_NODES / 128, H_HEADS), 256>>>(x, W);
    sij_kernel<<<dim3(N_NODES / 8, H_HEADS), 256>>>(a);
    agg_kernel<<<dim3(N_NODES / 64, H_HEADS), 128>>>(out);
}